// round 1
// baseline (speedup 1.0000x reference)
#include <cuda_runtime.h>
#include <cuda_bf16.h>
#include <cstdint>

// ---------------- problem constants ----------------
#define BB   2
#define CC   128
#define HH   128
#define WW   128
#define HL   64
#define WL   64
#define QQ   65536
#define BQ   (BB*QQ)          // 131072
#define RTOT (4*BQ)           // 524288
#define HID  256
#define K0R  262              // real in_dim
#define K0P  272              // padded to 16*17

// ---------------- device scratch (static; no allocation) ----------------
__device__ float g_featT[(size_t)BB*HH*WW*CC];     // NHWC feat   (16.8 MB)
__device__ float g_lrT  [(size_t)BB*HL*WL*CC];     // NHWC lr     ( 4.2 MB)
__device__ float g_predArea[(size_t)RTOT*4];       // pred.xyz + area (33.5 MB)

// ---------------- f32x2 helpers ----------------
__device__ __forceinline__ unsigned long long pack2(float x, float y) {
    unsigned long long r;
    asm("mov.b64 %0, {%1, %2};" : "=l"(r) : "f"(x), "f"(y));
    return r;
}
__device__ __forceinline__ void unpack2(unsigned long long v, float& x, float& y) {
    asm("mov.b64 {%0, %1}, %2;" : "=f"(x), "=f"(y) : "l"(v));
}
__device__ __forceinline__ void fma2(unsigned long long& d, unsigned long long a, unsigned long long b) {
    asm("fma.rn.f32x2 %0, %1, %2, %0;" : "+l"(d) : "l"(a), "l"(b));
}

// ---------------- kernel 1: NCHW -> NHWC tiled transpose (C = 128) ----------------
__global__ void transpose_kernel(const float* __restrict__ src, int Hh, int Ww, int mode)
{
    __shared__ float tile[32][33];
    float* dst = mode ? g_lrT : g_featT;
    const int x0 = blockIdx.x * 32;
    const int c0 = blockIdx.y * 32;
    const int bz = blockIdx.z;                 // b*Hh + y
    const int b  = bz / Hh, y = bz % Hh;
    const int txi = threadIdx.x, tyi = threadIdx.y;   // 32 x 8
#pragma unroll
    for (int j = 0; j < 4; j++) {
        int c = c0 + tyi + j * 8;
        tile[tyi + j * 8][txi] =
            src[(((size_t)b * CC + c) * Hh + y) * Ww + x0 + txi];
    }
    __syncthreads();
#pragma unroll
    for (int j = 0; j < 4; j++) {
        int x = x0 + tyi + j * 8;
        dst[(((size_t)b * Hh + y) * Ww + x) * CC + c0 + txi] = tile[txi][tyi + j * 8];
    }
}

// ---------------- fused MLP layer (64 rows x 256 cols, K-major SMEM activations) ----
// thread grid 16x16: thread(ty,tx) owns rows 4*ty..+3, cols 16*tx..+15 (as 8 col-pairs)
template<int KREAL, int KPAD, bool RELU>
__device__ __forceinline__ void mlp_layer(const float* __restrict__ Wg,
                                          const float* __restrict__ bg,
                                          const float* __restrict__ inBuf,
                                          float* __restrict__ outBuf,
                                          float* __restrict__ wt,
                                          float* __restrict__ bias,
                                          int tx, int ty)
{
    const int t = threadIdx.x;
    __syncthreads();                     // previous layer fully done
    bias[t] = bg[t];
    __syncthreads();

    const int c0 = tx * 16;
    unsigned long long acc[4][8];
#pragma unroll
    for (int cp = 0; cp < 8; cp++) {
        unsigned long long bb = pack2(bias[c0 + 2 * cp], bias[c0 + 2 * cp + 1]);
#pragma unroll
        for (int r = 0; r < 4; r++) acc[r][cp] = bb;
    }

    constexpr int NKB = KPAD / 16;
    for (int kb = 0; kb < NKB; kb++) {
        __syncthreads();                 // wt reuse protection
#pragma unroll
        for (int i = 0; i < 4; i++) {    // stage 16x256 weight tile
            int fidx = (i * 256 + t) * 4;
            int gidx = kb * 4096 + fidx;
            float4 v = make_float4(0.f, 0.f, 0.f, 0.f);
            if (gidx < KREAL * 256) v = *(const float4*)(Wg + gidx);
            *(float4*)(wt + fidx) = v;
        }
        __syncthreads();
#pragma unroll
        for (int kk = 0; kk < 16; kk++) {
            float4 xv = *(const float4*)(inBuf + (kb * 16 + kk) * 64 + 4 * ty);
            const ulonglong2* wrow = (const ulonglong2*)(wt + kk * 256 + c0);
            ulonglong2 w01 = wrow[0], w23 = wrow[1], w45 = wrow[2], w67 = wrow[3];
            unsigned long long bcol[8] = { w01.x, w01.y, w23.x, w23.y,
                                           w45.x, w45.y, w67.x, w67.y };
            unsigned long long a0 = pack2(xv.x, xv.x);
            unsigned long long a1 = pack2(xv.y, xv.y);
            unsigned long long a2 = pack2(xv.z, xv.z);
            unsigned long long a3 = pack2(xv.w, xv.w);
#pragma unroll
            for (int cp = 0; cp < 8; cp++) {
                fma2(acc[0][cp], a0, bcol[cp]);
                fma2(acc[1][cp], a1, bcol[cp]);
                fma2(acc[2][cp], a2, bcol[cp]);
                fma2(acc[3][cp], a3, bcol[cp]);
            }
        }
    }
    // store transposed (K-major) for the next layer; outBuf disjoint from inBuf/wt
#pragma unroll
    for (int cp = 0; cp < 8; cp++) {
        float lo[4], hi[4];
#pragma unroll
        for (int r = 0; r < 4; r++) {
            unpack2(acc[r][cp], lo[r], hi[r]);
            if (RELU) { lo[r] = fmaxf(lo[r], 0.f); hi[r] = fmaxf(hi[r], 0.f); }
        }
        *(float4*)(outBuf + (c0 + 2 * cp    ) * 64 + 4 * ty) = make_float4(lo[0], lo[1], lo[2], lo[3]);
        *(float4*)(outBuf + (c0 + 2 * cp + 1) * 64 + 4 * ty) = make_float4(hi[0], hi[1], hi[2], hi[3]);
    }
}

// ---------------- kernel 3: fused gather + 5-layer MLP ----------------
__global__ void __launch_bounds__(256, 1) mlp_kernel(
    const float* __restrict__ coord, const float* __restrict__ cell,
    const float* __restrict__ W0, const float* __restrict__ b0,
    const float* __restrict__ W1, const float* __restrict__ b1,
    const float* __restrict__ W2, const float* __restrict__ b2,
    const float* __restrict__ W3, const float* __restrict__ b3,
    const float* __restrict__ W4, const float* __restrict__ b4)
{
    extern __shared__ float smem[];
    float* bufA  = smem;                    // [272][64]
    float* bufB  = bufA + K0P * 64;         // [256][64]
    float* wt    = bufB + 256 * 64;         // [16][256]
    float* bias  = wt   + 16 * 256;         // [256]
    float* areaS = bias + 256;              // [64]

    const int t    = threadIdx.x;
    const int rowL = t >> 2;
    const int sub  = t & 3;
    const long rg  = (long)blockIdx.x * 64 + rowL;
    const int s    = (int)(rg >> 17);       // / BQ
    const int rem  = (int)(rg & (BQ - 1));  // b*Q + q
    const int b    = rem >> 16;             // / Q

    // ---- phase 0: per-row geometry + feature gathers into bufA (K-major) ----
    const float cy = coord[2 * rem + 0];
    const float cx = coord[2 * rem + 1];
    const float vx = (s & 2) ? 1.f : -1.f;
    const float vy = (s & 1) ? 1.f : -1.f;
    const float r128 = 1.f / 128.f;
    float cy_ = cy + (vx * r128 + 1e-6f);
    float cx_ = cx + (vy * r128 + 1e-6f);
    cy_ = fminf(fmaxf(cy_, -1.f + 1e-6f), 1.f - 1e-6f);
    cx_ = fminf(fmaxf(cx_, -1.f + 1e-6f), 1.f - 1e-6f);
    int iy  = (int)floorf(((cy_ + 1.f) * 128.f - 1.f) * 0.5f + 0.5f);
    int ix  = (int)floorf(((cx_ + 1.f) * 128.f - 1.f) * 0.5f + 0.5f);
    iy = min(max(iy, 0), 127); ix = min(max(ix, 0), 127);
    int liy = (int)floorf(((cy_ + 1.f) * 64.f - 1.f) * 0.5f + 0.5f);
    int lix = (int)floorf(((cx_ + 1.f) * 64.f - 1.f) * 0.5f + 0.5f);
    liy = min(max(liy, 0), 63); lix = min(max(lix, 0), 63);

    if (sub == 0) {
        float qy = -1.f + (2.f * (float)iy + 1.f) * r128;
        float qx = -1.f + (2.f * (float)ix + 1.f) * r128;
        float rel_y = (cy - qy) * 128.f;
        float rel_x = (cx - qx) * 128.f;
        bufA[128 * 64 + rowL] = rel_y;
        bufA[129 * 64 + rowL] = rel_x;
        bufA[258 * 64 + rowL] = -1.f + (2.f * (float)liy + 1.f) * (1.f / 64.f);
        bufA[259 * 64 + rowL] = -1.f + (2.f * (float)lix + 1.f) * (1.f / 64.f);
        bufA[260 * 64 + rowL] = cell[2 * rem + 0] * 128.f;
        bufA[261 * 64 + rowL] = cell[2 * rem + 1] * 128.f;
#pragma unroll
        for (int k = K0R; k < K0P; k++) bufA[k * 64 + rowL] = 0.f;  // zero pad
        areaS[rowL] = fabsf(rel_y * rel_x) + 1e-9f;
    }
    {   // hi-res features: channels [0..127]
        const float4* fb = (const float4*)(g_featT + (size_t)(((b * HH + iy) * WW + ix)) * CC);
#pragma unroll
        for (int i = 0; i < 8; i++) {
            float4 v = fb[sub * 8 + i];
            int c = (sub * 8 + i) * 4;
            bufA[(c + 0) * 64 + rowL] = v.x;
            bufA[(c + 1) * 64 + rowL] = v.y;
            bufA[(c + 2) * 64 + rowL] = v.z;
            bufA[(c + 3) * 64 + rowL] = v.w;
        }
        // lr features: channels [130..257]
        const float4* lb = (const float4*)(g_lrT + (size_t)(((b * HL + liy) * WL + lix)) * CC);
#pragma unroll
        for (int i = 0; i < 8; i++) {
            float4 v = lb[sub * 8 + i];
            int c = 130 + (sub * 8 + i) * 4;
            bufA[(c + 0) * 64 + rowL] = v.x;
            bufA[(c + 1) * 64 + rowL] = v.y;
            bufA[(c + 2) * 64 + rowL] = v.z;
            bufA[(c + 3) * 64 + rowL] = v.w;
        }
    }

    // ---- layers 0..3 ----
    const int tx = t & 15, ty = t >> 4;
    mlp_layer<K0R, K0P, true>(W0, b0, bufA, bufB, wt, bias, tx, ty);
    mlp_layer<256, 256, true>(W1, b1, bufB, bufA, wt, bias, tx, ty);
    mlp_layer<256, 256, true>(W2, b2, bufA, bufB, wt, bias, tx, ty);
    mlp_layer<256, 256, true>(W3, b3, bufB, bufA, wt, bias, tx, ty);

    // ---- layer 4: 256 -> 3, no relu; write pred + area ----
    __syncthreads();
    if (t < 192) {
#pragma unroll
        for (int i = 0; i < 4; i++) wt[t * 4 + i] = W4[t * 4 + i];   // 768 floats
    }
    if (t < 3) bias[t] = b4[t];
    __syncthreads();
    if (t < 192) {
        const int r  = t / 3;
        const int oc = t - 3 * r;
        float acc = bias[oc];
#pragma unroll 16
        for (int k = 0; k < 256; k++)
            acc = fmaf(bufA[k * 64 + r], wt[k * 3 + oc], acc);
        const size_t rgi = (size_t)((long)blockIdx.x * 64 + r) * 4;
        g_predArea[rgi + oc] = acc;
        if (oc == 0) g_predArea[rgi + 3] = areaS[r];
    }
}

// ---------------- kernel 4: local-ensemble combine (diagonal area swap) -------------
__global__ void combine_kernel(float* __restrict__ out)
{
    const int idx = blockIdx.x * 256 + threadIdx.x;     // b*Q + q
    const float4 p0 = *(const float4*)(g_predArea + ((size_t)(0 * BQ + idx)) * 4);
    const float4 p1 = *(const float4*)(g_predArea + ((size_t)(1 * BQ + idx)) * 4);
    const float4 p2 = *(const float4*)(g_predArea + ((size_t)(2 * BQ + idx)) * 4);
    const float4 p3 = *(const float4*)(g_predArea + ((size_t)(3 * BQ + idx)) * 4);
    const float tot = p0.w + p1.w + p2.w + p3.w;
    const float w0 = p3.w / tot, w1 = p2.w / tot, w2 = p1.w / tot, w3 = p0.w / tot;
    out[idx * 3 + 0] = p0.x * w0 + p1.x * w1 + p2.x * w2 + p3.x * w3;
    out[idx * 3 + 1] = p0.y * w0 + p1.y * w1 + p2.y * w2 + p3.y * w3;
    out[idx * 3 + 2] = p0.z * w0 + p1.z * w1 + p2.z * w2 + p3.z * w3;
}

// ---------------- launch ----------------
extern "C" void kernel_launch(void* const* d_in, const int* in_sizes, int n_in,
                              void* d_out, int out_size)
{
    const float* feat  = (const float*)d_in[0];
    const float* lrft  = (const float*)d_in[1];
    const float* coord = (const float*)d_in[2];
    const float* cell  = (const float*)d_in[3];
    const float* W0 = (const float*)d_in[4];   const float* b0 = (const float*)d_in[5];
    const float* W1 = (const float*)d_in[6];   const float* b1 = (const float*)d_in[7];
    const float* W2 = (const float*)d_in[8];   const float* b2 = (const float*)d_in[9];
    const float* W3 = (const float*)d_in[10];  const float* b3 = (const float*)d_in[11];
    const float* W4 = (const float*)d_in[12];  const float* b4 = (const float*)d_in[13];
    float* out = (float*)d_out;

    const size_t SMEM_BYTES = (size_t)(K0P * 64 + 256 * 64 + 16 * 256 + 256 + 64) * sizeof(float);
    cudaFuncSetAttribute((const void*)mlp_kernel,
                         cudaFuncAttributeMaxDynamicSharedMemorySize, (int)SMEM_BYTES);

    dim3 blkT(32, 8);
    transpose_kernel<<<dim3(WW / 32, CC / 32, BB * HH), blkT>>>(feat, HH, WW, 0);
    transpose_kernel<<<dim3(WL / 32, CC / 32, BB * HL), blkT>>>(lrft, HL, WL, 1);

    mlp_kernel<<<RTOT / 64, 256, SMEM_BYTES>>>(coord, cell,
                                               W0, b0, W1, b1, W2, b2, W3, b3, W4, b4);

    combine_kernel<<<BQ / 256, 256>>>(out);
}

// round 3
// speedup vs baseline: 2.4857x; 2.4857x over previous
#include <cuda_runtime.h>
#include <cuda_bf16.h>
#include <cstdint>

// ---------------- problem constants ----------------
#define BB   2
#define CC   128
#define HH   128
#define WW   128
#define HL   64
#define WL   64
#define QQ   65536
#define BQ   (BB*QQ)          // 131072
#define RTOT (4*BQ)           // 524288
#define HID  256
#define K0R  262              // real in_dim
#define K0P  272              // padded to 16*17

typedef unsigned long long ull;

// ---------------- device scratch (static; no allocation) ----------------
__device__ float g_featT[(size_t)BB*HH*WW*CC];     // NHWC feat   (16.8 MB)
__device__ float g_lrT  [(size_t)BB*HL*WL*CC];     // NHWC lr     ( 4.2 MB)
__device__ float g_predArea[(size_t)RTOT*4];       // pred.xyz + area (33.5 MB)

// ---------------- f32x2 helpers ----------------
__device__ __forceinline__ ull pack2(float x, float y) {
    ull r;
    asm("mov.b64 %0, {%1, %2};" : "=l"(r) : "f"(x), "f"(y));
    return r;
}
__device__ __forceinline__ void unpack2(ull v, float& x, float& y) {
    asm("mov.b64 {%0, %1}, %2;" : "=f"(x), "=f"(y) : "l"(v));
}
__device__ __forceinline__ void fma2(ull& d, ull a, ull b) {
    asm("fma.rn.f32x2 %0, %1, %2, %0;" : "+l"(d) : "l"(a), "l"(b));
}

// P-layout address (floats) for activation element (c, r) in a [Kpad/2][32] unit grid.
// 16B unit (cpg, u) holds [A[2cpg][2u], A[2cpg+1][2u], A[2cpg][2u+1], A[2cpg+1][2u+1]],
// swizzled: unit index = cpg*32 + (u XOR (cpg & 31)).
__device__ __forceinline__ int paddr(int c, int r) {
    int cpg = c >> 1, u = r >> 1;
    return (cpg * 32 + (u ^ (cpg & 31))) * 4 + ((r & 1) << 1) + (c & 1);
}

// ---------------- kernel 1: NCHW -> NHWC tiled transpose (C = 128) ----------------
__global__ void transpose_kernel(const float* __restrict__ src, int Hh, int Ww, int mode)
{
    __shared__ float tile[32][33];
    float* dst = mode ? g_lrT : g_featT;
    const int x0 = blockIdx.x * 32;
    const int c0 = blockIdx.y * 32;
    const int bz = blockIdx.z;                 // b*Hh + y
    const int b  = bz / Hh, y = bz % Hh;
    const int txi = threadIdx.x, tyi = threadIdx.y;   // 32 x 8
#pragma unroll
    for (int j = 0; j < 4; j++) {
        int c = c0 + tyi + j * 8;
        tile[tyi + j * 8][txi] =
            src[(((size_t)b * CC + c) * Hh + y) * Ww + x0 + txi];
    }
    __syncthreads();
#pragma unroll
    for (int j = 0; j < 4; j++) {
        int x = x0 + tyi + j * 8;
        dst[(((size_t)b * Hh + y) * Ww + x) * CC + c0 + txi] = tile[txi][tyi + j * 8];
    }
}

// ---------------- fused MLP layer: 64 rows x 256 cols, P-layout activations ----------
// Thread map: tx = lane (0..31), ty = warp (0..7).
// Thread owns col-pairs {tx+32i, i=0..3} (cols 2tx+64i, +1) and rows 8ty..8ty+7.
template<int KREAL, int KPAD, bool RELU>
__device__ __forceinline__ void mlp_layer(const float* __restrict__ Wg,
                                          const float* __restrict__ bg,
                                          const float* __restrict__ inBuf,
                                          float* __restrict__ outBuf,
                                          float* __restrict__ wt,
                                          float* __restrict__ bias,
                                          int tx, int ty)
{
    const int t = threadIdx.x;
    __syncthreads();                     // previous layer fully done
    bias[t] = bg[t];
    __syncthreads();

    ull acc[4][8];
#pragma unroll
    for (int i = 0; i < 4; i++) {
        ull bp = *(const ull*)(bias + 2 * tx + 64 * i);   // (b[c0], b[c1]) LDS.64, conflict-free
#pragma unroll
        for (int r = 0; r < 8; r++) acc[i][r] = bp;
    }

    constexpr int NKB = KPAD / 16;
    for (int kb = 0; kb < NKB; kb++) {
        __syncthreads();                 // wt reuse protection
#pragma unroll
        for (int i = 0; i < 4; i++) {    // stage 16x256 weight tile (row-major, coalesced)
            int fidx = (i * 256 + t) * 4;
            int gidx = kb * 4096 + fidx;
            float4 v = make_float4(0.f, 0.f, 0.f, 0.f);
            if (KREAL == KPAD || gidx < KREAL * 256) v = *(const float4*)(Wg + gidx);
            *(float4*)(wt + fidx) = v;
        }
        __syncthreads();
#pragma unroll
        for (int p = 0; p < 8; p++) {                 // k-pair within tile
            const int cpg = kb * 8 + p;               // input col-pair index
            const int sw  = cpg & 31;
            float4 f[4];                              // rows 8ty..8ty+7 for k0,k1 (broadcast)
#pragma unroll
            for (int v = 0; v < 4; v++) {
                int u = 4 * ty + v;
                f[v] = *(const float4*)(inBuf + (cpg * 32 + (u ^ sw)) * 4);
            }
            ull w0[4], w1[4];                         // (w[k][c0], w[k][c1]) LDS.64, conflict-free
#pragma unroll
            for (int i = 0; i < 4; i++) {
                w0[i] = *(const ull*)(wt + (2 * p    ) * 256 + 2 * tx + 64 * i);
                w1[i] = *(const ull*)(wt + (2 * p + 1) * 256 + 2 * tx + 64 * i);
            }
#pragma unroll
            for (int v = 0; v < 4; v++) {
                ull a00 = pack2(f[v].x, f[v].x);      // act(k0, r=2v)
                ull a10 = pack2(f[v].y, f[v].y);      // act(k1, r=2v)
                ull a01 = pack2(f[v].z, f[v].z);      // act(k0, r=2v+1)
                ull a11 = pack2(f[v].w, f[v].w);      // act(k1, r=2v+1)
#pragma unroll
                for (int i = 0; i < 4; i++) {
                    fma2(acc[i][2 * v    ], a00, w0[i]);
                    fma2(acc[i][2 * v    ], a10, w1[i]);
                    fma2(acc[i][2 * v + 1], a01, w0[i]);
                    fma2(acc[i][2 * v + 1], a11, w1[i]);
                }
            }
        }
    }
    // epilogue: P-layout stores, bank = (4ty+v) XOR tx -> bijection, zero conflict
#pragma unroll
    for (int i = 0; i < 4; i++) {
        int cpg = tx + 32 * i;
        int sw  = cpg & 31;
#pragma unroll
        for (int v = 0; v < 4; v++) {
            float x0, y0, x1, y1;
            unpack2(acc[i][2 * v    ], x0, y0);
            unpack2(acc[i][2 * v + 1], x1, y1);
            if (RELU) {
                x0 = fmaxf(x0, 0.f); y0 = fmaxf(y0, 0.f);
                x1 = fmaxf(x1, 0.f); y1 = fmaxf(y1, 0.f);
            }
            int u = 4 * ty + v;
            *(float4*)(outBuf + (cpg * 32 + (u ^ sw)) * 4) = make_float4(x0, y0, x1, y1);
        }
    }
}

// ---------------- kernel 3: fused gather + 5-layer MLP ----------------
__global__ void __launch_bounds__(256, 1) mlp_kernel(
    const float* __restrict__ coord, const float* __restrict__ cell,
    const float* __restrict__ W0, const float* __restrict__ b0,
    const float* __restrict__ W1, const float* __restrict__ b1,
    const float* __restrict__ W2, const float* __restrict__ b2,
    const float* __restrict__ W3, const float* __restrict__ b3,
    const float* __restrict__ W4, const float* __restrict__ b4)
{
    extern __shared__ float smem[];
    float* bufA  = smem;                       // P-layout, 136 cpg x 32 units = 17408 floats
    float* bufB  = bufA + (K0P / 2) * 32 * 4;  // P-layout, 128 cpg            = 16384 floats
    float* wt    = bufB + 128 * 32 * 4;        // [16][256]
    float* bias  = wt   + 16 * 256;            // [256]
    float* areaS = bias + 256;                 // [64]

    const int t    = threadIdx.x;
    const int rowL = t >> 2;
    const int sub  = t & 3;
    const long rg  = (long)blockIdx.x * 64 + rowL;
    const int s    = (int)(rg >> 17);       // / BQ
    const int rem  = (int)(rg & (BQ - 1));  // b*Q + q
    const int b    = rem >> 16;             // / Q

    // ---- phase 0: per-row geometry + feature gathers into bufA (P-layout) ----
    const float cy = coord[2 * rem + 0];
    const float cx = coord[2 * rem + 1];
    const float vx = (s & 2) ? 1.f : -1.f;
    const float vy = (s & 1) ? 1.f : -1.f;
    const float r128 = 1.f / 128.f;
    float cy_ = cy + (vx * r128 + 1e-6f);
    float cx_ = cx + (vy * r128 + 1e-6f);
    cy_ = fminf(fmaxf(cy_, -1.f + 1e-6f), 1.f - 1e-6f);
    cx_ = fminf(fmaxf(cx_, -1.f + 1e-6f), 1.f - 1e-6f);
    int iy  = (int)floorf(((cy_ + 1.f) * 128.f - 1.f) * 0.5f + 0.5f);
    int ix  = (int)floorf(((cx_ + 1.f) * 128.f - 1.f) * 0.5f + 0.5f);
    iy = min(max(iy, 0), 127); ix = min(max(ix, 0), 127);
    int liy = (int)floorf(((cy_ + 1.f) * 64.f - 1.f) * 0.5f + 0.5f);
    int lix = (int)floorf(((cx_ + 1.f) * 64.f - 1.f) * 0.5f + 0.5f);
    liy = min(max(liy, 0), 63); lix = min(max(lix, 0), 63);

    if (sub == 0) {
        float qy = -1.f + (2.f * (float)iy + 1.f) * r128;
        float qx = -1.f + (2.f * (float)ix + 1.f) * r128;
        float rel_y = (cy - qy) * 128.f;
        float rel_x = (cx - qx) * 128.f;
        bufA[paddr(128, rowL)] = rel_y;
        bufA[paddr(129, rowL)] = rel_x;
        bufA[paddr(258, rowL)] = -1.f + (2.f * (float)liy + 1.f) * (1.f / 64.f);
        bufA[paddr(259, rowL)] = -1.f + (2.f * (float)lix + 1.f) * (1.f / 64.f);
        bufA[paddr(260, rowL)] = cell[2 * rem + 0] * 128.f;
        bufA[paddr(261, rowL)] = cell[2 * rem + 1] * 128.f;
#pragma unroll
        for (int k = K0R; k < K0P; k++) bufA[paddr(k, rowL)] = 0.f;  // zero pad
        areaS[rowL] = fabsf(rel_y * rel_x) + 1e-9f;
    }
    {   // hi-res features: channels [0..127]
        const float4* fb = (const float4*)(g_featT + (size_t)(((b * HH + iy) * WW + ix)) * CC);
#pragma unroll
        for (int i = 0; i < 8; i++) {
            float4 v = fb[sub * 8 + i];
            int c = (sub * 8 + i) * 4;
            bufA[paddr(c + 0, rowL)] = v.x;
            bufA[paddr(c + 1, rowL)] = v.y;
            bufA[paddr(c + 2, rowL)] = v.z;
            bufA[paddr(c + 3, rowL)] = v.w;
        }
        // lr features: channels [130..257]
        const float4* lb = (const float4*)(g_lrT + (size_t)(((b * HL + liy) * WL + lix)) * CC);
#pragma unroll
        for (int i = 0; i < 8; i++) {
            float4 v = lb[sub * 8 + i];
            int c = 130 + (sub * 8 + i) * 4;
            bufA[paddr(c + 0, rowL)] = v.x;
            bufA[paddr(c + 1, rowL)] = v.y;
            bufA[paddr(c + 2, rowL)] = v.z;
            bufA[paddr(c + 3, rowL)] = v.w;
        }
    }

    // ---- layers 0..3 ----
    const int tx = t & 31, ty = t >> 5;
    mlp_layer<K0R, K0P, true>(W0, b0, bufA, bufB, wt, bias, tx, ty);
    mlp_layer<256, 256, true>(W1, b1, bufB, bufA, wt, bias, tx, ty);
    mlp_layer<256, 256, true>(W2, b2, bufA, bufB, wt, bias, tx, ty);
    mlp_layer<256, 256, true>(W3, b3, bufB, bufA, wt, bias, tx, ty);

    // ---- layer 4: 256 -> 3, no relu; write pred + area ----
    __syncthreads();
    if (t < 192) {
#pragma unroll
        for (int i = 0; i < 4; i++) wt[t * 4 + i] = W4[t * 4 + i];   // 768 floats
    }
    if (t < 3) bias[t] = b4[t];
    __syncthreads();
    if (t < 192) {
        const int r  = t / 3;
        const int oc = t - 3 * r;
        float acc = bias[oc];
#pragma unroll 8
        for (int k = 0; k < 256; k++)
            acc = fmaf(bufA[paddr(k, r)], wt[k * 3 + oc], acc);
        const size_t rgi = (size_t)((long)blockIdx.x * 64 + r) * 4;
        g_predArea[rgi + oc] = acc;
        if (oc == 0) g_predArea[rgi + 3] = areaS[r];
    }
}

// ---------------- kernel 4: local-ensemble combine (diagonal area swap) -------------
__global__ void combine_kernel(float* __restrict__ out)
{
    const int idx = blockIdx.x * 256 + threadIdx.x;     // b*Q + q
    const float4 p0 = *(const float4*)(g_predArea + ((size_t)(0 * BQ + idx)) * 4);
    const float4 p1 = *(const float4*)(g_predArea + ((size_t)(1 * BQ + idx)) * 4);
    const float4 p2 = *(const float4*)(g_predArea + ((size_t)(2 * BQ + idx)) * 4);
    const float4 p3 = *(const float4*)(g_predArea + ((size_t)(3 * BQ + idx)) * 4);
    const float tot = p0.w + p1.w + p2.w + p3.w;
    const float w0 = p3.w / tot, w1 = p2.w / tot, w2 = p1.w / tot, w3 = p0.w / tot;
    out[idx * 3 + 0] = p0.x * w0 + p1.x * w1 + p2.x * w2 + p3.x * w3;
    out[idx * 3 + 1] = p0.y * w0 + p1.y * w1 + p2.y * w2 + p3.y * w3;
    out[idx * 3 + 2] = p0.z * w0 + p1.z * w1 + p2.z * w2 + p3.z * w3;
}

// ---------------- launch ----------------
extern "C" void kernel_launch(void* const* d_in, const int* in_sizes, int n_in,
                              void* d_out, int out_size)
{
    const float* feat  = (const float*)d_in[0];
    const float* lrft  = (const float*)d_in[1];
    const float* coord = (const float*)d_in[2];
    const float* cell  = (const float*)d_in[3];
    const float* W0 = (const float*)d_in[4];   const float* b0 = (const float*)d_in[5];
    const float* W1 = (const float*)d_in[6];   const float* b1 = (const float*)d_in[7];
    const float* W2 = (const float*)d_in[8];   const float* b2 = (const float*)d_in[9];
    const float* W3 = (const float*)d_in[10];  const float* b3 = (const float*)d_in[11];
    const float* W4 = (const float*)d_in[12];  const float* b4 = (const float*)d_in[13];
    float* out = (float*)d_out;

    const size_t SMEM_FLOATS = (size_t)(K0P / 2) * 32 * 4   // bufA 17408
                             + (size_t)128 * 32 * 4         // bufB 16384
                             + 16 * 256                     // wt
                             + 256                          // bias
                             + 64;                          // area
    const size_t SMEM_BYTES = SMEM_FLOATS * sizeof(float);  // ~152.8 KB
    cudaFuncSetAttribute((const void*)mlp_kernel,
                         cudaFuncAttributeMaxDynamicSharedMemorySize, (int)SMEM_BYTES);

    dim3 blkT(32, 8);
    transpose_kernel<<<dim3(WW / 32, CC / 32, BB * HH), blkT>>>(feat, HH, WW, 0);
    transpose_kernel<<<dim3(WL / 32, CC / 32, BB * HL), blkT>>>(lrft, HL, WL, 1);

    mlp_kernel<<<RTOT / 64, 256, SMEM_BYTES>>>(coord, cell,
                                               W0, b0, W1, b1, W2, b2, W3, b3, W4, b4);

    combine_kernel<<<BQ / 256, 256>>>(out);
}